// round 11
// baseline (speedup 1.0000x reference)
#include <cuda_runtime.h>
#include <cuda_bf16.h>
#include <math.h>

// Fixed shapes: cls_conv_out (4, 1029, 100, 100) fp32; rois (2000,4) int32.
// Only batch 3 used. Output (2000, 21, 1, 1) fp32.
#define KK       7
#define C1       21
#define NJL      49
#define H        100
#define W        100
#define HP       101
#define ROW_S    2124                 // HP*C1=2121 padded to mult of 4 (16B-aligned rows)
#define PLANE_S  (HP * ROW_S)
#define IN_BASE  (3 * 1029 * 10000)   // batch 3 offset
#define RPB      4                    // y-rows per block in kernel A

// Integral image, transposed c-innermost: I[jl][y][x][c]; ~42 MB scratch.
__device__ float g_integral[(size_t)NJL * PLANE_S];

// ---------------------------------------------------------------------------
// Kernel A: block = (jl, 4 y-rows), 21 warps = one channel each.
// Each warp: 4 float4 loads (rows r..r+3 of its channel), ONE 25-lane shuffle
// scan per row, conflict-free STS into the final transposed row layout,
// then thread 0 issues 4 cp.async.bulk row stores (tail wait amortized 4x).
// ---------------------------------------------------------------------------
__global__ void __launch_bounds__(672) build_xsum(const float* __restrict__ in) {
    const int ybase = RPB * blockIdx.x + 1;  // 1, 5, ..., 97
    const int jl    = blockIdx.y;            // 0..48
    const int t     = threadIdx.x;
    const int c     = t >> 5;                // warp id == channel 0..20
    const int lane  = t & 31;

    __shared__ __align__(16) float smt[RPB][ROW_S];  // final rows: smt[r][x*21+c]

    // zero x=0 column (21 floats) and tail padding (3 floats) of each row buf
    if (t < 24) {
        const int idx = (t < C1) ? t : (2121 + t - C1);
        #pragma unroll
        for (int r = 0; r < RPB; r++) smt[r][idx] = 0.0f;
    }

    // --- loads: lane l holds float4 covering x = 4l..4l+3 of each row
    const float4* src4 = (const float4*)(in + IN_BASE
                        + (size_t)jl * (C1 * H * W) + (size_t)c * (H * W));
    float4 v[RPB];
    if (lane < 25) {
        #pragma unroll
        for (int r = 0; r < RPB; r++)
            v[r] = src4[(ybase - 1 + r) * (W / 4) + lane];
    }

    // --- per-row: in-thread scan of 4 + one shfl_up scan over lanes,
    // scatter-store into transposed layout (out position x+1).
    // STS banks: (84*l + 21*i + 21 + c)/4 mod 32 = (21*l + const) mod 32,
    // 21 coprime 32 -> all 25 lanes distinct banks (conflict-free).
    #pragma unroll
    for (int r = 0; r < RPB; r++) {
        float s0 = v[r].x;
        float s1 = s0 + v[r].y;
        float s2 = s1 + v[r].z;
        float s3 = s2 + v[r].w;
        float run = s3;
        #pragma unroll
        for (int d = 1; d < 32; d <<= 1) {
            float u = __shfl_up_sync(0xffffffffu, run, d);
            if (lane >= d) run += u;
        }
        const float off = run - s3;
        if (lane < 25) {
            float* sl = smt[r] + 84 * lane + C1 + c;
            sl[0]      = off + s0;
            sl[C1]     = off + s1;
            sl[2 * C1] = off + s2;
            sl[3 * C1] = off + s3;
        }
    }
    __syncthreads();

    // --- 4 bulk async row stores, single wait
    if (t == 0) {
        asm volatile("fence.proxy.async.shared::cta;" ::: "memory");
        float* gd = g_integral + ((size_t)jl * HP + ybase) * ROW_S;
        #pragma unroll
        for (int r = 0; r < RPB; r++) {
            unsigned sa;
            asm("{ .reg .u64 a; cvta.to.shared.u64 a, %1; cvt.u32.u64 %0, a; }"
                : "=r"(sa) : "l"(smt[r]));
            asm volatile(
                "cp.async.bulk.global.shared::cta.bulk_group [%0], [%1], %2;"
                :: "l"(gd + (size_t)r * ROW_S), "r"(sa), "r"(ROW_S * 4) : "memory");
        }
        asm volatile("cp.async.bulk.commit_group;" ::: "memory");
        asm volatile("cp.async.bulk.wait_group 0;" ::: "memory");
    }
}

// ---------------------------------------------------------------------------
// Kernel B: y-cumsum over float2 slots (1062/row); writes y=0 zero row then
// 100 dependent FADD2 steps, unroll 10 for load MLP.
// ---------------------------------------------------------------------------
__global__ void build_ysum() {
    const int jl    = blockIdx.y;
    const int slot2 = blockIdx.x * blockDim.x + threadIdx.x;
    if (slot2 >= ROW_S / 2) return;

    float2* p = (float2*)(g_integral + (size_t)jl * PLANE_S) + slot2;
    const int stride2 = ROW_S / 2;      // 1062

    float2 acc = make_float2(0.f, 0.f);
    p[0] = acc;                         // y = 0 row is zero
    #pragma unroll 10
    for (int y = 1; y <= H; y++) {
        float2 v = p[(size_t)y * stride2];
        acc.x += v.x; acc.y += v.y;
        p[(size_t)y * stride2] = acc;
    }
}

// ---------------------------------------------------------------------------
// Kernel C: one block per ROI. 336 active threads (16 jl-groups x 21 c);
// per-thread register pre-reduction, 21-thread final sum, warp softmax.
// ---------------------------------------------------------------------------
__global__ void pool_softmax(const int* __restrict__ rois,
                             float* __restrict__ out) {
    const int roi = blockIdx.x;
    const int t   = threadIdx.x;
    __shared__ float s_part[336];      // [jl0*21 + c]
    __shared__ float s_avg[C1];

    const int4 r = ((const int4*)rois)[roi];   // ymin, xmin, ymax, xmax
    const int ys = (r.z - r.x) / KK;
    const int xs = (r.w - r.y) / KK;

    if (t < 336) {
        const int c   = t % C1;
        const int jl0 = t / C1;   // 0..15
        float part = 0.0f;
        #pragma unroll
        for (int jl = jl0; jl < NJL; jl += 16) {
            const int j = jl / KK, l = jl - j * KK;
            const int y0 = r.x + j * ys, y1 = y0 + ys;
            const int x0 = r.y + l * xs, x1 = x0 + xs;
            const float* P = g_integral + (size_t)jl * PLANE_S;
            const float a = P[(size_t)y1 * ROW_S + x1 * C1 + c];
            const float b = P[(size_t)y0 * ROW_S + x1 * C1 + c];
            const float d = P[(size_t)y1 * ROW_S + x0 * C1 + c];
            const float e = P[(size_t)y0 * ROW_S + x0 * C1 + c];
            part += (a - b) - (d - e);
        }
        s_part[t] = part;
    }
    __syncthreads();

    if (t < C1) {
        float acc = 0.0f;
        #pragma unroll
        for (int g = 0; g < 16; g++) acc += s_part[g * C1 + t];
        s_avg[t] = acc / (49.0f * (float)(ys * xs));
    }
    __syncthreads();

    if (t < 32) {
        const bool act = t < C1;
        float v = act ? s_avg[t] : -INFINITY;
        float m = v;
        #pragma unroll
        for (int o = 16; o; o >>= 1) m = fmaxf(m, __shfl_xor_sync(0xffffffffu, m, o));
        float e = act ? expf(v - m) : 0.0f;
        float sum = e;
        #pragma unroll
        for (int o = 16; o; o >>= 1) sum += __shfl_xor_sync(0xffffffffu, sum, o);
        if (act) out[(size_t)roi * C1 + t] = e / sum;
    }
}

// ---------------------------------------------------------------------------
extern "C" void kernel_launch(void* const* d_in, const int* in_sizes, int n_in,
                              void* d_out, int out_size) {
    const float* x    = (const float*)d_in[0];
    const int*   rois = (const int*)d_in[1];
    float*       out  = (float*)d_out;
    const int n_rois  = in_sizes[1] / 4;   // 2000

    dim3 gA(H / RPB, NJL);                  // 25 x 49
    build_xsum<<<gA, 672>>>(x);

    dim3 gB((ROW_S / 2 + 127) / 128, NJL);  // 9 x 49
    build_ysum<<<gB, 128>>>();

    pool_softmax<<<n_rois, 352>>>(rois, out);
}